// round 11
// baseline (speedup 1.0000x reference)
#include <cuda_runtime.h>
#include <cuda_bf16.h>
#include <cstdint>
#include <math.h>
#include <float.h>

#define BB   4
#define NN   4096
#define DD   1024
#define WW   128
#define NWIN (NN / WW)          // 32
#define MTOT (BB * NN)          // 16384

// ---------------------------------------------------------------------------
// bf16 hi/lo split scratch. ONLY referenced from device code — NEVER passed
// as kernel args from host (host-side &symbol is the shadow copy; GB300 ATS
// makes writes to it silently land in host memory).
// ---------------------------------------------------------------------------
__device__ __nv_bfloat16 g_x_hi  [(size_t)MTOT * DD];
__device__ __nv_bfloat16 g_x_lo  [(size_t)MTOT * DD];
__device__ __nv_bfloat16 g_wqk_hi[(size_t)2048 * DD];   // [n][k] = w_qkv[k][n]
__device__ __nv_bfloat16 g_wqk_lo[(size_t)2048 * DD];
__device__ __nv_bfloat16 g_wo_hi [(size_t)1024 * DD];   // [n][k] = w_out[k][n]
__device__ __nv_bfloat16 g_wo_lo [(size_t)1024 * DD];
__device__ __nv_bfloat16 g_q_hi  [(size_t)MTOT * DD];
__device__ __nv_bfloat16 g_q_lo  [(size_t)MTOT * DD];
__device__ __nv_bfloat16 g_k_hi  [(size_t)MTOT * DD];
__device__ __nv_bfloat16 g_k_lo  [(size_t)MTOT * DD];
__device__ __nv_bfloat16 g_kT_hi [(size_t)BB * DD * NN]; // [b][d][t]
__device__ __nv_bfloat16 g_kT_lo [(size_t)BB * DD * NN];
__device__ __nv_bfloat16 g_attn_hi[(size_t)MTOT * 256];  // unnormalized exp
__device__ __nv_bfloat16 g_attn_lo[(size_t)MTOT * 256];
__device__ __nv_bfloat16 g_ao_hi [(size_t)MTOT * DD];
__device__ __nv_bfloat16 g_ao_lo [(size_t)MTOT * DD];
__device__ float         g_invsum[MTOT];

// ---------------------------------------------------------------------------
// primitives
// ---------------------------------------------------------------------------
__device__ __forceinline__ uint32_t smem_u32(const void* p) {
    uint32_t a;
    asm("{ .reg .u64 t; cvta.to.shared.u64 t, %1; cvt.u32.u64 %0, t; }"
        : "=r"(a) : "l"(p));
    return a;
}

__device__ __forceinline__ void mma16816(float* c, const uint32_t* a, const uint32_t* b) {
    asm volatile(
        "mma.sync.aligned.m16n8k16.row.col.f32.bf16.bf16.f32 "
        "{%0,%1,%2,%3}, {%4,%5,%6,%7}, {%8,%9}, {%0,%1,%2,%3};"
        : "+f"(c[0]), "+f"(c[1]), "+f"(c[2]), "+f"(c[3])
        : "r"(a[0]), "r"(a[1]), "r"(a[2]), "r"(a[3]), "r"(b[0]), "r"(b[1]));
}

__device__ __forceinline__ void ldsm_x4(uint32_t& d0, uint32_t& d1,
                                        uint32_t& d2, uint32_t& d3, uint32_t a) {
    asm volatile("ldmatrix.sync.aligned.m8n8.x4.shared.b16 {%0,%1,%2,%3}, [%4];"
                 : "=r"(d0), "=r"(d1), "=r"(d2), "=r"(d3) : "r"(a));
}

__device__ __forceinline__ void cp16(uint32_t dst, const void* src) {
    asm volatile("cp.async.cg.shared.global [%0], [%1], 16;"
                 :: "r"(dst), "l"(src) : "memory");
}
#define CP_COMMIT() asm volatile("cp.async.commit_group;" ::: "memory")
#define CP_WAIT1()  asm volatile("cp.async.wait_group 1;" ::: "memory")
#define CP_WAIT0()  asm volatile("cp.async.wait_group 0;" ::: "memory")

__device__ __forceinline__ void f2bf_split(float v, __nv_bfloat16& hi, __nv_bfloat16& lo) {
    hi = __float2bfloat16(v);
    lo = __float2bfloat16(v - __bfloat162float(hi));
}

// ============================================================================
// Kernel A (stages 1,2): 512 threads, CTA tile 128x256 — UNCHANGED from R10
// ============================================================================
// smem per buffer: K-chunk 32 -> 64B data + 16B pad = 80B row stride.
#define RS    80
#define A_HI  0
#define A_LO  10240
#define B_HI  20480
#define B_LO  40960
#define BUFB  61440
#define NBUF  3
#define SMEMB (NBUF * BUFB)     // 184320; stg 128*257*4=131584 aliases it
#define NT    512               // 16 warps: 4x4 warp grid, warp tile 32x64

__device__ __forceinline__ void load_chunk_async(
    char* sm, uint32_t smb, int cc, int bufIdx, int stage, int w, int t,
    const __nv_bfloat16* Ah, const __nv_bfloat16* Al,
    const __nv_bfloat16* Bh, const __nv_bfloat16* Bl,
    long long aBase, long long bBase, int Astr, int Bstr)
{
    const int kE = cc * 32;
    const uint32_t bo = (uint32_t)bufIdx * BUFB;
    const uint4 z = make_uint4(0u, 0u, 0u, 0u);
    {
        const int r = t >> 2, sg = t & 3;
        const long long off = aBase + (long long)r * Astr + kE + sg * 8;
        const uint32_t d = smb + bo + A_HI + r * RS + sg * 16;
        cp16(d, Ah + off);
        cp16(d + (A_LO - A_HI), Al + off);
    }
    #pragma unroll
    for (int i = 0; i < 2; i++) {
        const int idx = t + i * NT;
        const int r = idx >> 2, sg = idx & 3;
        bool v = true;
        if (stage == 1) v = (w > 0) || (r >= 128);
        if (stage == 2) v = (w > 0) || (cc >= 4);
        const int o = B_HI + r * RS + sg * 16;
        if (v) {
            const long long off = bBase + (long long)r * Bstr + kE + sg * 8;
            cp16(smb + bo + o, Bh + off);
            cp16(smb + bo + o + (B_LO - B_HI), Bl + off);
        } else {
            *(uint4*)(sm + bo + o) = z;
            *(uint4*)(sm + bo + o + (B_LO - B_HI)) = z;
        }
    }
}

// one K-chunk (k=32, two k16 steps): bf16x3, warp tile 32x64 (shared by both
// kernels; aLo/bLo are the hi->lo smem deltas of the calling kernel's layout)
template <int ALO, int BLO>
__device__ __forceinline__ void compute_chunk(
    uint32_t bufAdd, const uint32_t* aAddr, const uint32_t* bAddr,
    float (&acc)[2][8][4])
{
    #pragma unroll
    for (int kk = 0; kk < 2; kk++) {
        const uint32_t kb = bufAdd + (uint32_t)kk * 32u;
        uint32_t A[2][4], B0[8][2], B1[8][2];
        #pragma unroll
        for (int fm = 0; fm < 2; fm++)
            ldsm_x4(A[fm][0], A[fm][1], A[fm][2], A[fm][3], aAddr[fm] + kb);
        #pragma unroll
        for (int p = 0; p < 4; p++)
            ldsm_x4(B0[2*p][0], B0[2*p][1], B0[2*p+1][0], B0[2*p+1][1],
                    bAddr[p] + kb);
        #pragma unroll
        for (int fm = 0; fm < 2; fm++)
            #pragma unroll
            for (int fn = 0; fn < 8; fn++)
                mma16816(acc[fm][fn], A[fm], B0[fn]);    // Ah*Bh
        #pragma unroll
        for (int p = 0; p < 4; p++)
            ldsm_x4(B1[2*p][0], B1[2*p][1], B1[2*p+1][0], B1[2*p+1][1],
                    bAddr[p] + kb + BLO);
        #pragma unroll
        for (int fm = 0; fm < 2; fm++)
            #pragma unroll
            for (int fn = 0; fn < 8; fn++)
                mma16816(acc[fm][fn], A[fm], B1[fn]);    // Ah*Bl
        #pragma unroll
        for (int fm = 0; fm < 2; fm++)
            ldsm_x4(A[fm][0], A[fm][1], A[fm][2], A[fm][3],
                    aAddr[fm] + kb + ALO);
        #pragma unroll
        for (int fm = 0; fm < 2; fm++)
            #pragma unroll
            for (int fn = 0; fn < 8; fn++)
                mma16816(acc[fm][fn], A[fm], B0[fn]);    // Al*Bh
    }
}

__global__ void __launch_bounds__(NT, 1) mma_gemm(int stage,
                                                  float* __restrict__ dOut,
                                                  const float* __restrict__ bias)
{
    extern __shared__ char sm[];
    const uint32_t smb = smem_u32(sm);
    const int t = threadIdx.x;
    const int lane = t & 31, wid = t >> 5;
    const int wm = wid & 3, wn = wid >> 2;     // 4 M-slices x 4 N-slices
    const int g = lane >> 2, tg = lane & 3;

    int b = 0, w = 0;
    if (stage == 1) { w = blockIdx.x; b = blockIdx.y; }
    else            { w = blockIdx.y; b = blockIdx.z; }   // stage 2
    const int n0 = (stage == 2) ? blockIdx.x * 256 : 0;

    const int NCH = (stage == 2) ? 8 : 32;

    const __nv_bfloat16 *Ah, *Al, *Bh, *Bl;
    long long aBase, bBase;
    int Astr, Bstr;
    if (stage == 1) {
        Ah = g_q_hi;  Al = g_q_lo;  Bh = g_k_hi;   Bl = g_k_lo;
        aBase = ((long long)b * NN + (long long)w * WW) * DD;
        bBase = ((long long)b * NN + (long long)(w - 1) * WW) * DD;
        Astr = DD; Bstr = DD;
    } else {
        Ah = g_attn_hi; Al = g_attn_lo; Bh = g_kT_hi; Bl = g_kT_lo;
        aBase = ((long long)(b * NWIN + w) * WW) * 256;
        bBase = ((long long)(b * DD + n0)) * NN + (long long)(w - 1) * WW;
        Astr = 256; Bstr = NN;
    }

    uint32_t aAddr[2], bAddr[4];
    {
        const int rowA = lane & 15;
        const int khA  = (lane >> 4) * 16;
        #pragma unroll
        for (int fm = 0; fm < 2; fm++)
            aAddr[fm] = smb + A_HI + (uint32_t)((wm * 32 + fm * 16 + rowA) * RS + khA);
        const int rowB = (lane & 7) + ((lane >> 4) & 1) * 8;
        const int khB  = ((lane >> 3) & 1) * 16;
        #pragma unroll
        for (int p = 0; p < 4; p++)
            bAddr[p] = smb + B_HI + (uint32_t)((wn * 64 + p * 16 + rowB) * RS + khB);
    }

    float acc[2][8][4];
    #pragma unroll
    for (int i = 0; i < 2; i++)
        #pragma unroll
        for (int j = 0; j < 8; j++)
            #pragma unroll
            for (int e = 0; e < 4; e++) acc[i][j][e] = 0.f;

    load_chunk_async(sm, smb, 0, 0, stage, w, t, Ah, Al, Bh, Bl, aBase, bBase, Astr, Bstr);
    CP_COMMIT();
    load_chunk_async(sm, smb, 1, 1, stage, w, t, Ah, Al, Bh, Bl, aBase, bBase, Astr, Bstr);
    CP_COMMIT();

    #pragma unroll 1
    for (int c = 0; c < NCH; c++) {
        CP_WAIT1();
        __syncthreads();
        compute_chunk<(A_LO - A_HI), (B_LO - B_HI)>(
            (uint32_t)((c % 3) * BUFB), aAddr, bAddr, acc);
        const int cc = c + 2;
        if (cc < NCH)
            load_chunk_async(sm, smb, cc, cc % 3, stage, w, t,
                             Ah, Al, Bh, Bl, aBase, bBase, Astr, Bstr);
        CP_COMMIT();
    }
    __syncthreads();

    float* stg = (float*)sm;
    #pragma unroll
    for (int fm = 0; fm < 2; fm++) {
        const int r0 = wm * 32 + fm * 16 + g;
        #pragma unroll
        for (int fn = 0; fn < 8; fn++) {
            const int c0 = wn * 64 + fn * 8 + tg * 2;
            stg[r0 * 257 + c0]           = acc[fm][fn][0];
            stg[r0 * 257 + c0 + 1]       = acc[fm][fn][1];
            stg[(r0 + 8) * 257 + c0]     = acc[fm][fn][2];
            stg[(r0 + 8) * 257 + c0 + 1] = acc[fm][fn][3];
        }
    }
    __syncthreads();

    const int wg = wid;
    const int col = t & 255;
    const int rb  = t >> 8;
    if (stage == 1) {
        const int rowbase = (b * NWIN + w) * WW;
        for (int rr = 0; rr < 8; rr++) {
            const int r = wg * 8 + rr;
            float vv[8];
            float mx = -FLT_MAX;
            #pragma unroll
            for (int u = 0; u < 8; u++) {
                int j = lane + u * 32;
                float sc = stg[r * 257 + j] * 0.03125f;
                vv[u] = (j <= r + 128) ? sc : -FLT_MAX;
                mx = fmaxf(mx, vv[u]);
            }
            #pragma unroll
            for (int off = 16; off; off >>= 1)
                mx = fmaxf(mx, __shfl_xor_sync(0xffffffffu, mx, off));
            float sum = 0.f;
            #pragma unroll
            for (int u = 0; u < 8; u++) {
                int j = lane + u * 32;
                float e = (j <= r + 128) ? expf(vv[u] - mx) : 0.f;
                sum += e;
                __nv_bfloat16 hi, lo; f2bf_split(e, hi, lo);
                size_t o = (size_t)(rowbase + r) * 256 + j;
                g_attn_hi[o] = hi; g_attn_lo[o] = lo;
            }
            #pragma unroll
            for (int off = 16; off; off >>= 1)
                sum += __shfl_xor_sync(0xffffffffu, sum, off);
            if (lane == 0) g_invsum[rowbase + r] = 1.f / sum;
        }
    } else {
        const int rowbase = (b * NWIN + w) * WW;
        #pragma unroll 4
        for (int rr = 0; rr < 64; rr++) {
            const int r = rb + rr * 2;
            float v = stg[r * 257 + col] * g_invsum[rowbase + r];
            __nv_bfloat16 hi, lo; f2bf_split(v, hi, lo);
            size_t o = ((size_t)b * NN + (size_t)w * WW + r) * DD + n0 + col;
            g_ao_hi[o] = hi; g_ao_lo[o] = lo;
        }
    }
}

// ============================================================================
// Kernel B (stages 0,3): 256 threads, CTA tile 128x128, 2 CTAs/SM
// ============================================================================
#define RS2    80
#define A2_HI  0
#define A2_LO  10240
#define B2_HI  20480
#define B2_LO  30720
#define BUFB2  40960
#define SMEMB2 (2 * BUFB2)      // 81920; stg 128*129*4=66048 aliases it

__device__ __forceinline__ void load_chunk2(
    uint32_t smb, int cc, int bufIdx, int t,
    const __nv_bfloat16* Ah, const __nv_bfloat16* Al,
    const __nv_bfloat16* Bh, const __nv_bfloat16* Bl,
    long long aBase, long long bBase)
{
    const int kE = cc * 32;
    const uint32_t bo = (uint32_t)bufIdx * BUFB2;
    // A: 128 rows x 4 segs; B: 128 rows x 4 segs; 256 threads -> 2 segs each
    #pragma unroll
    for (int i = 0; i < 2; i++) {
        const int idx = t + i * 256;
        const int r = idx >> 2, sg = idx & 3;
        const long long offA = aBase + (long long)r * DD + kE + sg * 8;
        const long long offB = bBase + (long long)r * DD + kE + sg * 8;
        const uint32_t dA = smb + bo + A2_HI + r * RS2 + sg * 16;
        const uint32_t dB = smb + bo + B2_HI + r * RS2 + sg * 16;
        cp16(dA, Ah + offA);
        cp16(dA + (A2_LO - A2_HI), Al + offA);
        cp16(dB, Bh + offB);
        cp16(dB + (B2_LO - B2_HI), Bl + offB);
    }
}

__global__ void __launch_bounds__(256, 2) mma_gemm2(int stage,
                                                    float* __restrict__ dOut,
                                                    const float* __restrict__ bias)
{
    extern __shared__ char sm[];
    const uint32_t smb = smem_u32(sm);
    const int t = threadIdx.x;
    const int lane = t & 31, wid = t >> 5;
    const int wm = wid & 3, wn = wid >> 2;     // 4 M-slices x 2 N-slices
    const int g = lane >> 2, tg = lane & 3;

    const int n0 = blockIdx.x * 128;
    const int m0 = blockIdx.y * 128;

    const __nv_bfloat16 *Ah, *Al, *Bh, *Bl;
    if (stage == 0) { Ah = g_x_hi;  Al = g_x_lo;  Bh = g_wqk_hi; Bl = g_wqk_lo; }
    else            { Ah = g_ao_hi; Al = g_ao_lo; Bh = g_wo_hi;  Bl = g_wo_lo; }
    const long long aBase = (long long)m0 * DD;
    const long long bBase = (long long)n0 * DD;

    uint32_t aAddr[2], bAddr[4];
    {
        const int rowA = lane & 15;
        const int khA  = (lane >> 4) * 16;
        #pragma unroll
        for (int fm = 0; fm < 2; fm++)
            aAddr[fm] = smb + A2_HI + (uint32_t)((wm * 32 + fm * 16 + rowA) * RS2 + khA);
        const int rowB = (lane & 7) + ((lane >> 4) & 1) * 8;
        const int khB  = ((lane >> 3) & 1) * 16;
        #pragma unroll
        for (int p = 0; p < 4; p++)
            bAddr[p] = smb + B2_HI + (uint32_t)((wn * 64 + p * 16 + rowB) * RS2 + khB);
    }

    float acc[2][8][4];
    #pragma unroll
    for (int i = 0; i < 2; i++)
        #pragma unroll
        for (int j = 0; j < 8; j++)
            #pragma unroll
            for (int e = 0; e < 4; e++) acc[i][j][e] = 0.f;

    const int NCH = 32;
    load_chunk2(smb, 0, 0, t, Ah, Al, Bh, Bl, aBase, bBase);
    CP_COMMIT();

    #pragma unroll 1
    for (int c = 0; c < NCH; c++) {
        CP_WAIT0();                // chunk c resident
        __syncthreads();           // all warps done with buffer (c+1)&1's old data
        const int cc = c + 1;
        if (cc < NCH)
            load_chunk2(smb, cc, cc & 1, t, Ah, Al, Bh, Bl, aBase, bBase);
        CP_COMMIT();
        compute_chunk<(A2_LO - A2_HI), (B2_LO - B2_HI)>(
            (uint32_t)((c & 1) * BUFB2), aAddr, bAddr, acc);
    }
    __syncthreads();

    // stage D[128,128] into smem [128][129] fp32 (aliases buffers)
    float* stg = (float*)sm;
    #pragma unroll
    for (int fm = 0; fm < 2; fm++) {
        const int r0 = wm * 32 + fm * 16 + g;
        #pragma unroll
        for (int fn = 0; fn < 8; fn++) {
            const int c0 = wn * 64 + fn * 8 + tg * 2;
            stg[r0 * 129 + c0]           = acc[fm][fn][0];
            stg[r0 * 129 + c0 + 1]       = acc[fm][fn][1];
            stg[(r0 + 8) * 129 + c0]     = acc[fm][fn][2];
            stg[(r0 + 8) * 129 + c0 + 1] = acc[fm][fn][3];
        }
    }
    __syncthreads();

    const int col = t & 127;
    const int rb  = t >> 7;        // 0 or 1
    if (stage == 0) {
        const bool isQ = (n0 < 1024);
        __nv_bfloat16* dh = isQ ? g_q_hi : g_k_hi;
        __nv_bfloat16* dl = isQ ? g_q_lo : g_k_lo;
        const int nq = isQ ? n0 : (n0 - 1024);
        #pragma unroll 4
        for (int rr = 0; rr < 64; rr++) {
            const int r = rb + rr * 2;
            float v = stg[r * 129 + col];
            __nv_bfloat16 hi, lo; f2bf_split(v, hi, lo);
            size_t o = (size_t)(m0 + r) * DD + nq + col;
            dh[o] = hi; dl[o] = lo;
        }
    } else {
        const float bv = bias[n0 + col];
        #pragma unroll 4
        for (int rr = 0; rr < 64; rr++) {
            const int r = rb + rr * 2;
            dOut[(size_t)(m0 + r) * DD + n0 + col] = stg[r * 129 + col] + bv;
        }
    }
}

// ---------------------------------------------------------------------------
// Converters — destinations are device globals referenced IN DEVICE CODE ONLY
// ---------------------------------------------------------------------------
__global__ void convert_x_kernel(const float* __restrict__ x)
{
    size_t i = ((size_t)blockIdx.x * blockDim.x + threadIdx.x) * 4;
    float4 v = *(const float4*)(x + i);
    float vals[4] = { v.x, v.y, v.z, v.w };
    #pragma unroll
    for (int j = 0; j < 4; j++) {
        __nv_bfloat16 hi, lo; f2bf_split(vals[j], hi, lo);
        g_x_hi[i + j] = hi;
        g_x_lo[i + j] = lo;
    }
}

// dst[n][k] = src[k][n], bf16 hi/lo split; which: 0 -> wqk, 1 -> wo.
__global__ void transpose_convert_w(const float* __restrict__ src, int ld, int which)
{
    __nv_bfloat16* dh = (which == 0) ? g_wqk_hi : g_wo_hi;
    __nv_bfloat16* dl = (which == 0) ? g_wqk_lo : g_wo_lo;
    __shared__ float sh[32][33];
    const int n0 = blockIdx.x * 32, k0 = blockIdx.y * 32;
    const int tx = threadIdx.x, ty = threadIdx.y;
    #pragma unroll
    for (int i = 0; i < 4; i++)
        sh[ty + 8 * i][tx] = src[(size_t)(k0 + ty + 8 * i) * ld + n0 + tx];
    __syncthreads();
    #pragma unroll
    for (int i = 0; i < 4; i++) {
        float v = sh[tx][ty + 8 * i];
        int n = n0 + ty + 8 * i, k = k0 + tx;
        __nv_bfloat16 hi, lo; f2bf_split(v, hi, lo);
        dh[(size_t)n * DD + k] = hi;
        dl[(size_t)n * DD + k] = lo;
    }
}

// kT[b][d][t] = k[b][t][d]. grid: (1024/32, 4096/32, 4), block (32,8)
__global__ void transpose_k_kernel()
{
    __shared__ __nv_bfloat16 shh[32][34];
    __shared__ __nv_bfloat16 shl[32][34];
    const int d0 = blockIdx.x * 32, t0 = blockIdx.y * 32, b = blockIdx.z;
    const int tx = threadIdx.x, ty = threadIdx.y;
    #pragma unroll
    for (int i = 0; i < 4; i++) {
        int tok = t0 + ty + 8 * i;
        size_t o = ((size_t)b * NN + tok) * DD + d0 + tx;
        shh[ty + 8 * i][tx] = g_k_hi[o];
        shl[ty + 8 * i][tx] = g_k_lo[o];
    }
    __syncthreads();
    #pragma unroll
    for (int i = 0; i < 4; i++) {
        int d = d0 + ty + 8 * i;
        size_t o = ((size_t)b * DD + d) * NN + t0 + tx;
        g_kT_hi[o] = shh[tx][ty + 8 * i];
        g_kT_lo[o] = shl[tx][ty + 8 * i];
    }
}

// ---------------------------------------------------------------------------
extern "C" void kernel_launch(void* const* d_in, const int* in_sizes, int n_in,
                              void* d_out, int out_size)
{
    (void)in_sizes; (void)n_in; (void)out_size;
    const float* x     = (const float*)d_in[0];   // [4,4096,1024]
    const float* w_qkv = (const float*)d_in[1];   // [1024,3072]
    const float* w_out = (const float*)d_in[2];   // [1024,1024]
    const float* b_out = (const float*)d_in[3];   // [1024]
    float* out = (float*)d_out;                   // [4,4096,1024]

    cudaFuncSetAttribute(mma_gemm,  cudaFuncAttributeMaxDynamicSharedMemorySize, SMEMB);
    cudaFuncSetAttribute(mma_gemm2, cudaFuncAttributeMaxDynamicSharedMemorySize, SMEMB2);

    // 1) split inputs into bf16 hi/lo
    convert_x_kernel<<<MTOT * DD / 1024, 256>>>(x);
    transpose_convert_w<<<dim3(64, 32), dim3(32, 8)>>>(w_qkv, 3072, 0);
    transpose_convert_w<<<dim3(32, 32), dim3(32, 8)>>>(w_out, 1024, 1);

    // 2) qk = x @ w_qkv[:, :2048]   (128x128 tiles, 2 CTAs/SM)
    mma_gemm2<<<dim3(16, 128), 256, SMEMB2>>>(0, nullptr, nullptr);

    // 3) k transposed per batch for the attn*V GEMM
    transpose_k_kernel<<<dim3(32, 128, 4), dim3(32, 8)>>>();

    // 4) sim = q @ k2^T, softmax fused (unnormalized exp + invsum)
    mma_gemm<<<dim3(NWIN, BB), NT, SMEMB>>>(1, nullptr, nullptr);

    // 5) ao = attn @ k2 (values == keys per reference bug)
    mma_gemm<<<dim3(4, NWIN, BB), NT, SMEMB>>>(2, nullptr, nullptr);

    // 6) out = ao @ w_out + b_out  (128x128 tiles, 2 CTAs/SM)
    mma_gemm2<<<dim3(8, 128), 256, SMEMB2>>>(3, out, b_out);
}